// round 2
// baseline (speedup 1.0000x reference)
#include <cuda_runtime.h>

// GaussianNoiseLayer: per-row L2 clip to 3.0, then add pre-drawn noise.
// out[r, :] = x[r, :] * (3 / max(||x[r]||_2, 3)) + noise[r, :]
//
// One CTA per row (F = 4096 fp32 = 16 KB). Row is held in registers across
// the block reduction so x is read from HBM exactly once. Fully coalesced
// float4 traffic; kernel is HBM-bound (768 MB total floor).

#define FDIM 4096
#define THREADS 256
#define V4_PER_THREAD (FDIM / (THREADS * 4))   // = 4

__global__ void __launch_bounds__(THREADS)
clip_add_noise_kernel(const float* __restrict__ x,
                      const float* __restrict__ noise,
                      float* __restrict__ out)
{
    const long long row = blockIdx.x;
    const float4* __restrict__ xr = reinterpret_cast<const float4*>(x + row * FDIM);
    const float4* __restrict__ nr = reinterpret_cast<const float4*>(noise + row * FDIM);
    float4* __restrict__ orow = reinterpret_cast<float4*>(out + row * FDIM);

    const int t = threadIdx.x;

    // Load the whole row into registers; accumulate sum of squares.
    float4 v[V4_PER_THREAD];
    float ss = 0.0f;
#pragma unroll
    for (int i = 0; i < V4_PER_THREAD; i++) {
        v[i] = xr[t + i * THREADS];
        ss = fmaf(v[i].x, v[i].x, ss);
        ss = fmaf(v[i].y, v[i].y, ss);
        ss = fmaf(v[i].z, v[i].z, ss);
        ss = fmaf(v[i].w, v[i].w, ss);
    }

    // Warp reduce.
#pragma unroll
    for (int o = 16; o > 0; o >>= 1)
        ss += __shfl_xor_sync(0xffffffffu, ss, o);

    // Block reduce across 8 warps via shared memory.
    __shared__ float warpsum[THREADS / 32];
    const int wid = t >> 5;
    const int lid = t & 31;
    if (lid == 0) warpsum[wid] = ss;
    __syncthreads();

    float total = 0.0f;
#pragma unroll
    for (int w = 0; w < THREADS / 32; w++) total += warpsum[w];

    const float norm = sqrtf(total);
    const float scale = 3.0f / fmaxf(norm, 3.0f);

    // Scale + add noise, write back.
#pragma unroll
    for (int i = 0; i < V4_PER_THREAD; i++) {
        const float4 n = nr[t + i * THREADS];
        float4 o;
        o.x = fmaf(v[i].x, scale, n.x);
        o.y = fmaf(v[i].y, scale, n.y);
        o.z = fmaf(v[i].z, scale, n.z);
        o.w = fmaf(v[i].w, scale, n.w);
        orow[t + i * THREADS] = o;
    }
}

extern "C" void kernel_launch(void* const* d_in, const int* in_sizes, int n_in,
                              void* d_out, int out_size)
{
    const float* x     = (const float*)d_in[0];
    const float* noise = (const float*)d_in[1];
    float* out         = (float*)d_out;

    const int rows = in_sizes[0] / FDIM;   // 16384
    clip_add_noise_kernel<<<rows, THREADS>>>(x, noise, out);
}